// round 11
// baseline (speedup 1.0000x reference)
#include <cuda_runtime.h>

#define NB 16
#define NRR 300
#define CC 150
#define NRL 50
#define KK 10
#define MAXREC 100
#define NT 2700   // 300 * 9
#define NEG_INF (-3.0e38f)
#define FULLM 0xFFFFFFFFu

// Output layout (float elements), return order:
// so_pro_out (16,320,512), boxes_so_out (16,320,8), so_cls_out (16,320,300),
// rel_out (16,320,256), so_roi_out (16,320,12544), vis_out (16,300)
#define OFF_PRO 0
#define OFF_BOX 2621440
#define OFF_CLS 2662400
#define OFF_REL 4198400
#define OFF_ROI 5509120
#define OFF_VIS 69734400

__device__ int   g_ent[NB * KK];
__device__ float g_triple[NB * NT];
__device__ int   g_sc[NB * NRR * 3];
__device__ int   g_oc[NB * NRR * 3];
__device__ int   g_mi[NB * NRR];
__device__ float g_pure[NB * NRR];

__device__ __forceinline__ float sigm(float x) { return 1.0f / (1.0f + expf(-x)); }

__device__ __forceinline__ void better(float nv, int ni, float& bv, int& bi) {
    if (nv > bv || (nv == bv && ni < bi)) { bv = nv; bi = ni; }
}

// warp argmax (value desc, index asc), result broadcast to all lanes
__device__ __forceinline__ void warp_argmax(float& bv, int& bi) {
    #pragma unroll
    for (int off = 16; off > 0; off >>= 1) {
        float ov = __shfl_down_sync(FULLM, bv, off);
        int   oi = __shfl_down_sync(FULLM, bi, off);
        better(ov, oi, bv, bi);
    }
    bv = __shfl_sync(FULLM, bv, 0);
    bi = __shfl_sync(FULLM, bi, 0);
}

// ---------------------------------------------------------------------------
// K1: one warp per task, chip-wide. Tasks 0..4799: pair (n,p) -> triple scores
// + top3 classes. Tasks 4800..9599: entity (n,s) -> class argmax + sigmoid.
// ---------------------------------------------------------------------------
__global__ __launch_bounds__(256) void k1_pairs_entities(
    const float* __restrict__ so_class_logits,  // (16,300,300)
    const float* __restrict__ rel_logits,       // (16,300,50)
    const float* __restrict__ class_logits)     // (16,600,150)
{
    const int w    = blockIdx.x * 8 + (threadIdx.x >> 5);
    const int lane = threadIdx.x & 31;

    if (w < NB * NRR) {
        const int n = w / NRR, p = w % NRR;
        const float* sl = so_class_logits + (n * NRR + p) * (2 * CC);
        const float* rl = rel_logits + (n * NRR + p) * NRL;

        float sv[5], ov[5]; int sidx[5];
        #pragma unroll
        for (int k = 0; k < 5; k++) {
            int c = lane + 32 * k;
            bool ok = (c < CC);
            sidx[k] = ok ? c : (1 << 30);
            sv[k] = ok ? sl[c] : NEG_INF;
            ov[k] = ok ? sl[CC + c] : NEG_INF;
        }
        float r = (lane < NRL) ? rl[lane] : NEG_INF;
        if (lane + 32 < NRL) r = fmaxf(r, rl[lane + 32]);
        #pragma unroll
        for (int off = 16; off > 0; off >>= 1)
            r = fmaxf(r, __shfl_xor_sync(FULLM, r, off));
        float relm = sigm(r);

        float stv[3]; int sti[3];
        #pragma unroll
        for (int rnd = 0; rnd < 3; rnd++) {
            float bv = NEG_INF; int bi = (1 << 30);
            #pragma unroll
            for (int k = 0; k < 5; k++) better(sv[k], sidx[k], bv, bi);
            warp_argmax(bv, bi);
            stv[rnd] = bv; sti[rnd] = bi;
            #pragma unroll
            for (int k = 0; k < 5; k++) if (sidx[k] == bi) sv[k] = NEG_INF;
        }
        float otv[3]; int oti[3];
        #pragma unroll
        for (int rnd = 0; rnd < 3; rnd++) {
            float bv = NEG_INF; int bi = (1 << 30);
            #pragma unroll
            for (int k = 0; k < 5; k++) better(ov[k], sidx[k], bv, bi);
            warp_argmax(bv, bi);
            otv[rnd] = bv; oti[rnd] = bi;
            #pragma unroll
            for (int k = 0; k < 5; k++) if (sidx[k] == bi) ov[k] = NEG_INF;
        }

        float ss0 = sigm(stv[0]), ss1 = sigm(stv[1]), ss2 = sigm(stv[2]);
        float os0 = sigm(otv[0]), os1 = sigm(otv[1]), os2 = sigm(otv[2]);

        if (lane < 9) {
            int i = lane / 3, j = lane % 3;
            float ssv = (i == 0) ? ss0 : (i == 1) ? ss1 : ss2;
            float oov = (j == 0) ? os0 : (j == 1) ? os1 : os2;
            g_triple[n * NT + p * 9 + lane] = (relm * ssv) * oov;
        }
        if (lane < 3) {
            g_sc[(n * NRR + p) * 3 + lane] = sti[lane];
            g_oc[(n * NRR + p) * 3 + lane] = oti[lane];
        }
    } else if (w < 2 * NB * NRR) {
        const int q = w - NB * NRR;
        const int n = q / NRR, s = q % NRR;
        const float* cl = class_logits + (n * 2 * NRR + 2 * s) * CC;
        float bv = NEG_INF; int bi = (1 << 30);
        #pragma unroll
        for (int k = 0; k < 5; k++) {
            int c = lane + 32 * k;
            if (c < CC) better(cl[c], c, bv, bi);
        }
        warp_argmax(bv, bi);
        if (lane == 0) {
            g_mi[n * NRR + s]   = bi;
            g_pure[n * NRR + s] = sigm(bv);
        }
    }
}

// ---------------------------------------------------------------------------
// K2: per image (16 blocks x 1024). Top-100 triples, IoU dedup, top-10
// entities, vis_out, g_ent.
// ---------------------------------------------------------------------------
__global__ __launch_bounds__(1024) void k2_select(
    const float* __restrict__ pred_bboxes,     // (16,600,4)
    const float* __restrict__ pred_bboxes_so,  // (16,300,8)
    const unsigned char* __restrict__ vis,     // (16,300)
    float* __restrict__ out_vis)
{
    __shared__ float sh_triple[NT];
    __shared__ int   sh_selt[MAXREC];
    __shared__ int   sh_eq[128];
    __shared__ int   sh_cnt, sh_cnt_gt, sh_cnt_eq;
    __shared__ int   sel_class[2 * MAXREC];
    __shared__ float sel_box[2 * MAXREC * 4];
    __shared__ float sel_a2[2 * MAXREC];
    __shared__ float sh_score[NRR];
    __shared__ unsigned char sh_sel[NRR];
    __shared__ int   sh_ent[KK];
    __shared__ unsigned long long sh_key;

    const int n = blockIdx.x;
    const int tid = threadIdx.x;
    const int wid = tid >> 5;
    const int lane = tid & 31;

    for (int t = tid; t < NT; t += 1024) sh_triple[t] = g_triple[n * NT + t];
    if (tid < NRR) sh_sel[tid] = 0;
    __syncthreads();

    // --- top-100 threshold via binary search on float bits (values in (0,1)) ---
    unsigned lo = 0u, hi = 0x3F800000u;
    while (lo < hi) {
        unsigned mid = lo + ((hi - lo + 1u) >> 1);
        if (tid == 0) sh_cnt = 0;
        __syncthreads();
        int local = 0;
        for (int t = tid; t < NT; t += 1024)
            local += (__float_as_uint(sh_triple[t]) >= mid) ? 1 : 0;
        #pragma unroll
        for (int off = 16; off > 0; off >>= 1)
            local += __shfl_xor_sync(FULLM, local, off);
        if (lane == 0 && local) atomicAdd(&sh_cnt, local);
        __syncthreads();
        if (sh_cnt >= MAXREC) lo = mid; else hi = mid - 1u;
        __syncthreads();
    }
    const unsigned thr = lo;

    if (tid == 0) { sh_cnt_gt = 0; sh_cnt_eq = 0; }
    __syncthreads();
    for (int t = tid; t < NT; t += 1024) {
        unsigned b = __float_as_uint(sh_triple[t]);
        if (b > thr) {
            int p = atomicAdd(&sh_cnt_gt, 1);
            if (p < MAXREC) sh_selt[p] = t;
        } else if (b == thr) {
            int p = atomicAdd(&sh_cnt_eq, 1);
            if (p < 128) sh_eq[p] = t;
        }
    }
    __syncthreads();
    if (tid == 0) {
        int c1 = sh_cnt_gt; if (c1 > MAXREC) c1 = MAXREC;
        int need = MAXREC - c1;
        int ne = sh_cnt_eq; if (ne > 128) ne = 128;
        for (int a = 1; a < ne; a++) {   // ties: lowest index first
            int key = sh_eq[a]; int b = a - 1;
            while (b >= 0 && sh_eq[b] > key) { sh_eq[b + 1] = sh_eq[b]; b--; }
            sh_eq[b + 1] = key;
        }
        for (int a = 0; a < need && a < ne; a++) sh_selt[c1 + a] = sh_eq[a];
    }
    __syncthreads();

    // --- build selected (class, box, area): 200 entries ---
    if (tid < MAXREC) {
        int t = sh_selt[tid];
        int p = t / 9, r2 = t % 9, si = r2 / 3, oj = r2 % 3;
        const float* b = pred_bboxes_so + (n * NRR + p) * 8;
        sel_class[2 * tid]     = g_sc[(n * NRR + p) * 3 + si];
        sel_class[2 * tid + 1] = g_oc[(n * NRR + p) * 3 + oj];
        #pragma unroll
        for (int c = 0; c < 4; c++) {
            sel_box[(2 * tid) * 4 + c]     = b[c];
            sel_box[(2 * tid + 1) * 4 + c] = b[4 + c];
        }
        sel_a2[2 * tid]     = (b[3] - b[1] + 1.f) * (b[2] - b[0] + 1.f);
        sel_a2[2 * tid + 1] = (b[7] - b[5] + 1.f) * (b[6] - b[4] + 1.f);
    }
    __syncthreads();

    // --- entity scores: warp per entity, candidate loop over lanes ---
    for (int s = wid; s < NRR; s += 32) {
        int   mi   = g_mi[n * NRR + s];
        float pure = g_pure[n * NRR + s];
        const float* bp = pred_bboxes + (n * 2 * NRR + 2 * s) * 4;
        float x1 = bp[0], y1 = bp[1], x2 = bp[2], y2 = bp[3];
        float a1 = (y2 - y1 + 1.f) * (x2 - x1 + 1.f);
        bool fhit = false;
        for (int m = lane; m < 2 * MAXREC; m += 32) {
            if (sel_class[m] == mi) {
                float lx = fmaxf(x1, sel_box[m * 4 + 0]);
                float ly = fmaxf(y1, sel_box[m * 4 + 1]);
                float rx = fminf(x2, sel_box[m * 4 + 2]);
                float ry = fminf(y2, sel_box[m * 4 + 3]);
                float wdt = fmaxf(rx - lx, 0.f), hgt = fmaxf(ry - ly, 0.f);
                float inter = wdt * hgt;
                if (inter / (a1 + sel_a2[m] - inter) >= 0.5f) fhit = true;
            }
        }
        bool hit = __any_sync(FULLM, fhit);
        if (lane == 0)
            sh_score[s] = pure - (hit ? 2.f : 0.f)
                               - (vis[n * NRR + s] ? 2.f : 0.f);
    }
    __syncthreads();

    // --- top-10 entities via packed atomicMax (score desc, index asc) ---
    unsigned long long mykey = 0ull;
    if (tid < NRR) {
        float f = sh_score[tid];
        unsigned u = __float_as_uint(f);
        u ^= (u & 0x80000000u) ? 0xFFFFFFFFu : 0x80000000u;
        mykey = ((unsigned long long)u << 32) | (unsigned)(1023 - tid);
    }
    for (int k = 0; k < KK; k++) {
        if (tid == 0) sh_key = 0ull;
        __syncthreads();
        if (tid < NRR && !sh_sel[tid]) atomicMax(&sh_key, mykey);
        __syncthreads();
        if (tid == 0) {
            int s = 1023 - (int)(unsigned)(sh_key & 0xFFFFFFFFull);
            sh_ent[k] = s;
            sh_sel[s] = 1;
        }
        __syncthreads();
    }
    if (tid == 0) {
        for (int a = 1; a < KK; a++) {   // sort ascending
            int key = sh_ent[a]; int b = a - 1;
            while (b >= 0 && sh_ent[b] > key) { sh_ent[b + 1] = sh_ent[b]; b--; }
            sh_ent[b + 1] = key;
        }
        #pragma unroll
        for (int a = 0; a < KK; a++) g_ent[n * KK + a] = sh_ent[a];
    }
    __syncthreads();

    if (tid < NRR)
        out_vis[n * NRR + tid] = (vis[n * NRR + tid] || sh_sel[tid]) ? 1.0f : 0.0f;
}

// ---------------------------------------------------------------------------
// Main copy kernel: the 300 selection-independent rows of all 5 outputs.
// ---------------------------------------------------------------------------
#define S_ROI4 15052800u
#define S_PRO4   614400u
#define S_CLS4   360000u
#define S_REL4   307200u
#define S_BOX4     9600u
#define TOTM (S_ROI4+S_PRO4+S_CLS4+S_REL4+S_BOX4)   // 16344000

__device__ __forceinline__ void copy_main(const float4* __restrict__ src,
                                          float4* __restrict__ out,
                                          unsigned r, unsigned D4, unsigned off4)
{
    unsigned n = r / (NRR * D4);
    unsigned rem = r - n * (NRR * D4);
    unsigned row = rem / D4;
    unsigned col = rem - row * D4;
    out[off4 + (n * 320u + row) * D4 + col] = src[r];
}

__global__ __launch_bounds__(256) void main_copy_kernel(
    const float4* __restrict__ so_roi,     // (16,300,3136) f4
    const float4* __restrict__ so_pro,     // (16,300,128) f4
    const float4* __restrict__ so_cls,     // (16,300,75) f4
    const float4* __restrict__ rel_feat,   // (16,300,64) f4
    const float4* __restrict__ boxes_so,   // (16,300,2) f4
    float4* __restrict__ out)
{
    unsigned i = blockIdx.x * 256u + threadIdx.x;
    if (i < S_ROI4) { copy_main(so_roi, out, i, 3136u, OFF_ROI / 4u); return; }
    i -= S_ROI4;
    if (i < S_PRO4) { copy_main(so_pro, out, i, 128u, OFF_PRO / 4u); return; }
    i -= S_PRO4;
    if (i < S_CLS4) { copy_main(so_cls, out, i, 75u, OFF_CLS / 4u); return; }
    i -= S_CLS4;
    if (i < S_REL4) { copy_main(rel_feat, out, i, 64u, OFF_REL / 4u); return; }
    i -= S_REL4;
    if (i < S_BOX4) { copy_main(boxes_so, out, i, 2u, OFF_BOX / 4u); return; }
}

// ---------------------------------------------------------------------------
// Aux copy kernel: the 20 gathered rows per output (float4 tasks).
// ---------------------------------------------------------------------------
#define A_ROI4  1003520u   // 16*20*3136
#define A_PRO4    40960u   // 16*20*128
#define A_REL4    20480u   // 16*20*64
#define A_BOX4      640u   // 16*20*2
#define A_CLST    24000u   // 16*20*75 (float4 store, scalar loads)
#define TOTA (A_ROI4+A_PRO4+A_REL4+A_BOX4+A_CLST)   // 1089600

__global__ __launch_bounds__(256) void aux_copy_kernel(
    const float4* __restrict__ roi_feat,   // (16,300,3136) f4
    const float4* __restrict__ pro_feat,   // (16,300,128) f4
    const float4* __restrict__ aux_rel,    // (16,300,128) f4
    const float4* __restrict__ pred_bb,    // (16,600,4) floats = 600 f4/image
    const float* __restrict__ class_logits,// (16,600,150)
    float4* __restrict__ out)
{
    unsigned i = blockIdx.x * 256u + threadIdx.x;

    if (i < A_ROI4) {
        unsigned n = i / (20u * 3136u), rem = i % (20u * 3136u);
        unsigned j = rem / 3136u, c4 = rem % 3136u;
        unsigned e = (unsigned)g_ent[n * KK + (j % 10u)];
        unsigned c2 = (j < 10u) ? c4 : (c4 < 1568u ? c4 + 1568u : c4 - 1568u);
        out[OFF_ROI / 4u + (n * 320u + 300u + j) * 3136u + c4] =
            roi_feat[(n * 300u + e) * 3136u + c2];
        return;
    }
    i -= A_ROI4;
    if (i < A_PRO4) {
        unsigned n = i / (20u * 128u), rem = i % (20u * 128u);
        unsigned j = rem / 128u, c4 = rem % 128u;
        unsigned e = (unsigned)g_ent[n * KK + (j % 10u)];
        unsigned c2 = (j < 10u) ? c4 : ((c4 + 64u) & 127u);
        out[OFF_PRO / 4u + (n * 320u + 300u + j) * 128u + c4] =
            pro_feat[(n * 300u + e) * 128u + c2];
        return;
    }
    i -= A_PRO4;
    if (i < A_REL4) {
        unsigned n = i / (20u * 64u), rem = i % (20u * 64u);
        unsigned j = rem / 64u, c4 = rem % 64u;
        unsigned e = (unsigned)g_ent[n * KK + (j % 10u)];
        unsigned c2 = c4 + ((j < 10u) ? 0u : 64u);
        out[OFF_REL / 4u + (n * 320u + 300u + j) * 64u + c4] =
            aux_rel[(n * 300u + e) * 128u + c2];
        return;
    }
    i -= A_REL4;
    if (i < A_BOX4) {
        unsigned n = i / (20u * 2u), rem = i % (20u * 2u);
        unsigned j = rem / 2u, c4 = rem % 2u;
        unsigned e = (unsigned)g_ent[n * KK + (j % 10u)];
        unsigned c2 = (j < 10u) ? c4 : (c4 ^ 1u);
        out[OFF_BOX / 4u + (n * 320u + 300u + j) * 2u + c4] =
            pred_bb[n * 600u + e * 2u + c2];
        return;
    }
    i -= A_BOX4;
    if (i < A_CLST) {
        unsigned n = i / (20u * 75u), rem = i % (20u * 75u);
        unsigned j = rem / 75u, c4 = rem % 75u;
        unsigned e = (unsigned)g_ent[n * KK + (j % 10u)];
        const float* src = class_logits + n * 90000u + e * 300u;
        float4 v;
        unsigned col = c4 * 4u;
        if (j < 10u) {
            v.x = src[col]; v.y = src[col + 1u];
            v.z = src[col + 2u]; v.w = src[col + 3u];
        } else {
            unsigned c0 = (col      < 150u) ? col + 150u : col - 150u;
            unsigned c1 = (col + 1u < 150u) ? col + 151u : col - 149u;
            unsigned c2 = (col + 2u < 150u) ? col + 152u : col - 148u;
            unsigned c3 = (col + 3u < 150u) ? col + 153u : col - 147u;
            v.x = src[c0]; v.y = src[c1]; v.z = src[c2]; v.w = src[c3];
        }
        out[OFF_CLS / 4u + (n * 320u + 300u + j) * 75u + c4] = v;
        return;
    }
}

// ---------------------------------------------------------------------------
// Launch: fork-join graph. Branch A (main stream): main_copy (big, independent).
// Branch B (side stream): k1 -> k2 -> aux_copy (selection chain).
// ---------------------------------------------------------------------------
extern "C" void kernel_launch(void* const* d_in, const int* in_sizes, int n_in,
                              void* d_out, int out_size)
{
    const float* aux_rel         = (const float*)d_in[0];
    const float* class_logits    = (const float*)d_in[1];
    const float* pred_bboxes     = (const float*)d_in[2];
    const float* pro_features    = (const float*)d_in[3];
    const float* roi_features    = (const float*)d_in[4];
    const float* so_class_logits = (const float*)d_in[5];
    const float* pred_bboxes_so  = (const float*)d_in[6];
    const float* so_pro          = (const float*)d_in[7];
    const float* so_roi          = (const float*)d_in[8];
    const float* rel_logits      = (const float*)d_in[9];
    const float* rel_feat        = (const float*)d_in[10];
    const unsigned char* vis     = (const unsigned char*)d_in[11];

    float* out = (float*)d_out;

    cudaStream_t s2;
    cudaStreamCreateWithFlags(&s2, cudaStreamNonBlocking);
    cudaEvent_t evFork, evJoin;
    cudaEventCreateWithFlags(&evFork, cudaEventDisableTiming);
    cudaEventCreateWithFlags(&evJoin, cudaEventDisableTiming);

    // fork: side stream joins the capture via event dependency
    cudaEventRecord(evFork, 0);
    cudaStreamWaitEvent(s2, evFork, 0);

    // Branch B: selection chain + aux gather (side stream)
    k1_pairs_entities<<<1200, 256, 0, s2>>>(so_class_logits, rel_logits,
                                            class_logits);
    k2_select<<<NB, 1024, 0, s2>>>(pred_bboxes, pred_bboxes_so, vis,
                                   out + OFF_VIS);
    aux_copy_kernel<<<(TOTA + 255u) / 256u, 256, 0, s2>>>(
        (const float4*)roi_features, (const float4*)pro_features,
        (const float4*)aux_rel, (const float4*)pred_bboxes,
        class_logits, (float4*)out);

    // Branch A: big selection-independent copy (main/legacy stream)
    main_copy_kernel<<<(TOTM + 255u) / 256u, 256>>>(
        (const float4*)so_roi, (const float4*)so_pro,
        (const float4*)so_class_logits, (const float4*)rel_feat,
        (const float4*)pred_bboxes_so, (float4*)out);

    // join
    cudaEventRecord(evJoin, s2);
    cudaStreamWaitEvent(0, evJoin, 0);

    cudaEventDestroy(evFork);
    cudaEventDestroy(evJoin);
    cudaStreamDestroy(s2);
}

// round 13
// speedup vs baseline: 1.3092x; 1.3092x over previous
#include <cuda_runtime.h>

#define NB 16
#define NRR 300
#define CC 150
#define NRL 50
#define KK 10
#define MAXREC 100
#define NT 2700   // 300 * 9
#define NEG_INF (-3.0e38f)
#define FULLM 0xFFFFFFFFu

// Output layout (float elements), return order:
// so_pro_out (16,320,512), boxes_so_out (16,320,8), so_cls_out (16,320,300),
// rel_out (16,320,256), so_roi_out (16,320,12544), vis_out (16,300)
#define OFF_PRO 0
#define OFF_BOX 2621440
#define OFF_CLS 2662400
#define OFF_REL 4198400
#define OFF_ROI 5509120
#define OFF_VIS 69734400

// copy region sizes (float4 tasks); main first, aux at the very end
#define S_ROI4 15052800u
#define S_PRO4   614400u
#define S_CLS4   360000u
#define S_REL4   307200u
#define S_BOX4     9600u
#define TOTM   16344000u
#define A_ROI4  1003520u
#define A_PRO4    40960u
#define A_REL4    20480u
#define A_BOX4      640u
#define A_CLST    24000u
#define TOTC   17433600u

// block layout
#define NK1        512
#define SEL_BASE   512
#define COPY_BASE  528
#define NCOPYBLK   68100
#define NGRID      68628
#define N_AUX_BLOCKS 4257   // copy blocks whose range touches [TOTM, TOTC)

__device__ int   g_ent[NB * KK];
__device__ float g_triple[NB * NT];
__device__ int   g_sc[NB * NRR * 3];
__device__ int   g_oc[NB * NRR * 3];
__device__ int   g_mi[NB * NRR];
__device__ float g_pure[NB * NRR];

// completion counters (self-resetting each launch)
__device__ int g_k1done  = 0;
__device__ int g_selpass = 0;
__device__ int g_seldone = 0;
__device__ int g_auxpass = 0;

__device__ __forceinline__ float sigm(float x) { return 1.0f / (1.0f + expf(-x)); }

__device__ __forceinline__ void better(float nv, int ni, float& bv, int& bi) {
    if (nv > bv || (nv == bv && ni < bi)) { bv = nv; bi = ni; }
}

__device__ __forceinline__ void warp_argmax(float& bv, int& bi) {
    #pragma unroll
    for (int off = 16; off > 0; off >>= 1) {
        float ov = __shfl_down_sync(FULLM, bv, off);
        int   oi = __shfl_down_sync(FULLM, bi, off);
        better(ov, oi, bv, bi);
    }
    bv = __shfl_sync(FULLM, bv, 0);
    bi = __shfl_sync(FULLM, bi, 0);
}

// ---------------------------------------------------------------------------
// k1 task: w in [0,4800) = pair, [4800,9600) = entity.
// ---------------------------------------------------------------------------
__device__ void do_k1_task(int w, int lane,
                           const float* __restrict__ so_class_logits,
                           const float* __restrict__ rel_logits,
                           const float* __restrict__ class_logits)
{
    if (w < NB * NRR) {
        const int n = w / NRR, p = w % NRR;
        const float* sl = so_class_logits + (n * NRR + p) * (2 * CC);
        const float* rl = rel_logits + (n * NRR + p) * NRL;

        float sv[5], ov[5]; int sidx[5];
        #pragma unroll
        for (int k = 0; k < 5; k++) {
            int c = lane + 32 * k;
            bool ok = (c < CC);
            sidx[k] = ok ? c : (1 << 30);
            sv[k] = ok ? sl[c] : NEG_INF;
            ov[k] = ok ? sl[CC + c] : NEG_INF;
        }
        float r = (lane < NRL) ? rl[lane] : NEG_INF;
        if (lane + 32 < NRL) r = fmaxf(r, rl[lane + 32]);
        #pragma unroll
        for (int off = 16; off > 0; off >>= 1)
            r = fmaxf(r, __shfl_xor_sync(FULLM, r, off));
        float relm = sigm(r);

        float stv[3]; int sti[3];
        #pragma unroll
        for (int rnd = 0; rnd < 3; rnd++) {
            float bv = NEG_INF; int bi = (1 << 30);
            #pragma unroll
            for (int k = 0; k < 5; k++) better(sv[k], sidx[k], bv, bi);
            warp_argmax(bv, bi);
            stv[rnd] = bv; sti[rnd] = bi;
            #pragma unroll
            for (int k = 0; k < 5; k++) if (sidx[k] == bi) sv[k] = NEG_INF;
        }
        float otv[3]; int oti[3];
        #pragma unroll
        for (int rnd = 0; rnd < 3; rnd++) {
            float bv = NEG_INF; int bi = (1 << 30);
            #pragma unroll
            for (int k = 0; k < 5; k++) better(ov[k], sidx[k], bv, bi);
            warp_argmax(bv, bi);
            otv[rnd] = bv; oti[rnd] = bi;
            #pragma unroll
            for (int k = 0; k < 5; k++) if (sidx[k] == bi) ov[k] = NEG_INF;
        }

        float ss0 = sigm(stv[0]), ss1 = sigm(stv[1]), ss2 = sigm(stv[2]);
        float os0 = sigm(otv[0]), os1 = sigm(otv[1]), os2 = sigm(otv[2]);

        if (lane < 9) {
            int i = lane / 3, j = lane % 3;
            float ssv = (i == 0) ? ss0 : (i == 1) ? ss1 : ss2;
            float oov = (j == 0) ? os0 : (j == 1) ? os1 : os2;
            g_triple[n * NT + p * 9 + lane] = (relm * ssv) * oov;
        }
        if (lane < 3) {
            g_sc[(n * NRR + p) * 3 + lane] = sti[lane];
            g_oc[(n * NRR + p) * 3 + lane] = oti[lane];
        }
    } else if (w < 2 * NB * NRR) {
        const int q = w - NB * NRR;
        const int n = q / NRR, s = q % NRR;
        const float* cl = class_logits + (n * 2 * NRR + 2 * s) * CC;
        float bv = NEG_INF; int bi = (1 << 30);
        #pragma unroll
        for (int k = 0; k < 5; k++) {
            int c = lane + 32 * k;
            if (c < CC) better(cl[c], c, bv, bi);
        }
        warp_argmax(bv, bi);
        if (lane == 0) {
            g_mi[n * NRR + s]   = bi;
            g_pure[n * NRR + s] = sigm(bv);
        }
    }
}

__device__ __forceinline__ void copy_main_task(const float4* __restrict__ src,
                                               float4* __restrict__ out,
                                               unsigned r, unsigned D4,
                                               unsigned off4)
{
    unsigned n = r / (NRR * D4);
    unsigned rem = r - n * (NRR * D4);
    unsigned row = rem / D4;
    unsigned col = rem - row * D4;
    out[off4 + (n * 320u + row) * D4 + col] = src[r];
}

__device__ __forceinline__ unsigned long long make_key(float f, int s) {
    unsigned u = __float_as_uint(f);
    u ^= (u & 0x80000000u) ? 0xFFFFFFFFu : 0x80000000u;
    return ((unsigned long long)u << 32) | (unsigned)(1023 - s);
}

// ---------------------------------------------------------------------------
// Mega-kernel
// ---------------------------------------------------------------------------
__global__ __launch_bounds__(256, 8) void mega_kernel(
    const float* __restrict__ so_class_logits,  // (16,300,300)
    const float* __restrict__ rel_logits,       // (16,300,50)
    const float* __restrict__ class_logits,     // (16,600,150)
    const float* __restrict__ pred_bboxes,      // (16,600,4)
    const float* __restrict__ pred_bboxes_so,   // (16,300,8)
    const unsigned char* __restrict__ vis,      // (16,300)
    const float* __restrict__ aux_rel,          // (16,300,512)
    const float* __restrict__ pro_features,     // (16,300,512)
    const float* __restrict__ roi_features,     // (16,300,12544)
    const float* __restrict__ so_pro,           // (16,300,512)
    const float* __restrict__ so_roi,           // (16,300,12544)
    const float* __restrict__ rel_feat,         // (16,300,256)
    float* __restrict__ outf)
{
    __shared__ float sh_triple[NT];
    __shared__ int   sh_selt[MAXREC];
    __shared__ int   sh_eq[128];
    __shared__ int   sh_cnt, sh_cnt_gt, sh_cnt_eq;
    __shared__ int   sel_class[2 * MAXREC];
    __shared__ float sel_box[2 * MAXREC * 4];
    __shared__ float sel_a2[2 * MAXREC];
    __shared__ float sh_score[NRR];
    __shared__ unsigned char sh_sel[NRR];
    __shared__ int   sh_ent[KK];
    __shared__ unsigned long long sh_key;

    const int bid = blockIdx.x;
    const int tid = threadIdx.x;
    const int wid = tid >> 5;
    const int lane = tid & 31;
    float4* out = (float4*)outf;

    if (bid < NK1) {
        // ================= k1 blocks =================
        int gw = bid * 8 + wid;
        do_k1_task(gw, lane, so_class_logits, rel_logits, class_logits);
        do_k1_task(gw + 4096, lane, so_class_logits, rel_logits, class_logits);
        if (gw + 8192 < 9600)
            do_k1_task(gw + 8192, lane, so_class_logits, rel_logits, class_logits);
        __syncthreads();
        if (tid == 0) {
            __threadfence();
            atomicAdd(&g_k1done, 1);
        }
        return;
    }

    if (bid < COPY_BASE) {
        // ================= select blocks (one per image) =================
        const int n = bid - SEL_BASE;

        // wait for k1
        if (tid == 0) {
            while (atomicAdd(&g_k1done, 0) < NK1) {}
            __threadfence();
            int v = atomicAdd(&g_selpass, 1);
            if (v == NB - 1) {             // last select block past the spin
                atomicExch(&g_selpass, 0);
                atomicExch(&g_k1done, 0);
            }
        }
        __syncthreads();

        for (int t = tid; t < NT; t += 256) sh_triple[t] = g_triple[n * NT + t];
        for (int s = tid; s < NRR; s += 256) sh_sel[s] = 0;
        __syncthreads();

        // top-100 threshold via binary search on float bits (values in (0,1))
        unsigned lo = 0u, hi = 0x3F800000u;
        while (lo < hi) {
            unsigned mid = lo + ((hi - lo + 1u) >> 1);
            if (tid == 0) sh_cnt = 0;
            __syncthreads();
            int local = 0;
            for (int t = tid; t < NT; t += 256)
                local += (__float_as_uint(sh_triple[t]) >= mid) ? 1 : 0;
            #pragma unroll
            for (int off = 16; off > 0; off >>= 1)
                local += __shfl_xor_sync(FULLM, local, off);
            if (lane == 0 && local) atomicAdd(&sh_cnt, local);
            __syncthreads();
            if (sh_cnt >= MAXREC) lo = mid; else hi = mid - 1u;
            __syncthreads();
        }
        const unsigned thr = lo;

        if (tid == 0) { sh_cnt_gt = 0; sh_cnt_eq = 0; }
        __syncthreads();
        for (int t = tid; t < NT; t += 256) {
            unsigned b = __float_as_uint(sh_triple[t]);
            if (b > thr) {
                int p = atomicAdd(&sh_cnt_gt, 1);
                if (p < MAXREC) sh_selt[p] = t;
            } else if (b == thr) {
                int p = atomicAdd(&sh_cnt_eq, 1);
                if (p < 128) sh_eq[p] = t;
            }
        }
        __syncthreads();
        if (tid == 0) {
            int c1 = sh_cnt_gt; if (c1 > MAXREC) c1 = MAXREC;
            int need = MAXREC - c1;
            int ne = sh_cnt_eq; if (ne > 128) ne = 128;
            for (int a = 1; a < ne; a++) {   // ties: lowest index first
                int key = sh_eq[a]; int b = a - 1;
                while (b >= 0 && sh_eq[b] > key) { sh_eq[b + 1] = sh_eq[b]; b--; }
                sh_eq[b + 1] = key;
            }
            for (int a = 0; a < need && a < ne; a++) sh_selt[c1 + a] = sh_eq[a];
        }
        __syncthreads();

        // build selected (class, box, area): 200 entries
        if (tid < MAXREC) {
            int t = sh_selt[tid];
            int p = t / 9, r2 = t % 9, si = r2 / 3, oj = r2 % 3;
            const float* b = pred_bboxes_so + (n * NRR + p) * 8;
            sel_class[2 * tid]     = g_sc[(n * NRR + p) * 3 + si];
            sel_class[2 * tid + 1] = g_oc[(n * NRR + p) * 3 + oj];
            #pragma unroll
            for (int c = 0; c < 4; c++) {
                sel_box[(2 * tid) * 4 + c]     = b[c];
                sel_box[(2 * tid + 1) * 4 + c] = b[4 + c];
            }
            sel_a2[2 * tid]     = (b[3] - b[1] + 1.f) * (b[2] - b[0] + 1.f);
            sel_a2[2 * tid + 1] = (b[7] - b[5] + 1.f) * (b[6] - b[4] + 1.f);
        }
        __syncthreads();

        // entity scores: warp per entity (8 warps), candidates over lanes
        for (int s = wid; s < NRR; s += 8) {
            int   mi   = g_mi[n * NRR + s];
            float pure = g_pure[n * NRR + s];
            const float* bp = pred_bboxes + (n * 2 * NRR + 2 * s) * 4;
            float x1 = bp[0], y1 = bp[1], x2 = bp[2], y2 = bp[3];
            float a1 = (y2 - y1 + 1.f) * (x2 - x1 + 1.f);
            bool fhit = false;
            for (int m = lane; m < 2 * MAXREC; m += 32) {
                if (sel_class[m] == mi) {
                    float lx = fmaxf(x1, sel_box[m * 4 + 0]);
                    float ly = fmaxf(y1, sel_box[m * 4 + 1]);
                    float rx = fminf(x2, sel_box[m * 4 + 2]);
                    float ry = fminf(y2, sel_box[m * 4 + 3]);
                    float wdt = fmaxf(rx - lx, 0.f), hgt = fmaxf(ry - ly, 0.f);
                    float inter = wdt * hgt;
                    if (inter / (a1 + sel_a2[m] - inter) >= 0.5f) fhit = true;
                }
            }
            bool hit = __any_sync(FULLM, fhit);
            if (lane == 0)
                sh_score[s] = pure - (hit ? 2.f : 0.f)
                                   - (vis[n * NRR + s] ? 2.f : 0.f);
        }
        __syncthreads();

        // top-10 via packed atomicMax (score desc, index asc)
        unsigned long long key0 = 0ull, key1 = 0ull;
        int s1 = tid + 256;
        if (tid < NRR) key0 = make_key(sh_score[tid], tid);
        if (s1 < NRR)  key1 = make_key(sh_score[s1], s1);
        for (int k = 0; k < KK; k++) {
            if (tid == 0) sh_key = 0ull;
            __syncthreads();
            if (tid < NRR && !sh_sel[tid]) atomicMax(&sh_key, key0);
            if (s1 < NRR && !sh_sel[s1])  atomicMax(&sh_key, key1);
            __syncthreads();
            if (tid == 0) {
                int s = 1023 - (int)(unsigned)(sh_key & 0xFFFFFFFFull);
                sh_ent[k] = s;
                sh_sel[s] = 1;
            }
            __syncthreads();
        }
        if (tid == 0) {
            for (int a = 1; a < KK; a++) {   // sort ascending
                int key = sh_ent[a]; int b = a - 1;
                while (b >= 0 && sh_ent[b] > key) { sh_ent[b + 1] = sh_ent[b]; b--; }
                sh_ent[b + 1] = key;
            }
            #pragma unroll
            for (int a = 0; a < KK; a++) g_ent[n * KK + a] = sh_ent[a];
            __threadfence();
            atomicAdd(&g_seldone, 1);   // release for aux copy blocks
        }

        // vis_out (no in-kernel consumer; harness reads after completion)
        for (int s = tid; s < NRR; s += 256)
            outf[OFF_VIS + n * NRR + s] =
                (vis[n * NRR + s] || sh_sel[s]) ? 1.0f : 0.0f;
        return;
    }

    // ================= copy blocks =================
    const unsigned cb = (unsigned)(bid - COPY_BASE);
    const unsigned base_i = cb * 256u;

    // aux-region blocks must wait for selection (scheduled many waves later,
    // so the spin is normally already satisfied)
    if (base_i + 255u >= TOTM) {
        if (tid == 0) {
            while (atomicAdd(&g_seldone, 0) < NB) {}
            __threadfence();
            int v = atomicAdd(&g_auxpass, 1);
            if (v == N_AUX_BLOCKS - 1) {    // last aux block past the spin
                atomicExch(&g_auxpass, 0);
                atomicExch(&g_seldone, 0);
            }
        }
        __syncthreads();
    }

    unsigned i = base_i + (unsigned)tid;

    // ---- main regions (selection-independent) ----
    if (i < S_ROI4) { copy_main_task((const float4*)so_roi, out, i, 3136u, OFF_ROI / 4u); return; }
    i -= S_ROI4;
    if (i < S_PRO4) { copy_main_task((const float4*)so_pro, out, i, 128u, OFF_PRO / 4u); return; }
    i -= S_PRO4;
    if (i < S_CLS4) { copy_main_task((const float4*)so_class_logits, out, i, 75u, OFF_CLS / 4u); return; }
    i -= S_CLS4;
    if (i < S_REL4) { copy_main_task((const float4*)rel_feat, out, i, 64u, OFF_REL / 4u); return; }
    i -= S_REL4;
    if (i < S_BOX4) { copy_main_task((const float4*)pred_bboxes_so, out, i, 2u, OFF_BOX / 4u); return; }
    i -= S_BOX4;

    // ---- aux regions (gathered rows 300..319) ----
    if (i < A_ROI4) {
        unsigned n = i / (20u * 3136u), rem = i % (20u * 3136u);
        unsigned j = rem / 3136u, c4 = rem % 3136u;
        unsigned e = (unsigned)g_ent[n * KK + (j % 10u)];
        unsigned c2 = (j < 10u) ? c4 : (c4 < 1568u ? c4 + 1568u : c4 - 1568u);
        out[OFF_ROI / 4u + (n * 320u + 300u + j) * 3136u + c4] =
            ((const float4*)roi_features)[(n * 300u + e) * 3136u + c2];
        return;
    }
    i -= A_ROI4;
    if (i < A_PRO4) {
        unsigned n = i / (20u * 128u), rem = i % (20u * 128u);
        unsigned j = rem / 128u, c4 = rem % 128u;
        unsigned e = (unsigned)g_ent[n * KK + (j % 10u)];
        unsigned c2 = (j < 10u) ? c4 : ((c4 + 64u) & 127u);
        out[OFF_PRO / 4u + (n * 320u + 300u + j) * 128u + c4] =
            ((const float4*)pro_features)[(n * 300u + e) * 128u + c2];
        return;
    }
    i -= A_PRO4;
    if (i < A_REL4) {
        unsigned n = i / (20u * 64u), rem = i % (20u * 64u);
        unsigned j = rem / 64u, c4 = rem % 64u;
        unsigned e = (unsigned)g_ent[n * KK + (j % 10u)];
        unsigned c2 = c4 + ((j < 10u) ? 0u : 64u);
        out[OFF_REL / 4u + (n * 320u + 300u + j) * 64u + c4] =
            ((const float4*)aux_rel)[(n * 300u + e) * 128u + c2];
        return;
    }
    i -= A_REL4;
    if (i < A_BOX4) {
        unsigned n = i / (20u * 2u), rem = i % (20u * 2u);
        unsigned j = rem / 2u, c4 = rem % 2u;
        unsigned e = (unsigned)g_ent[n * KK + (j % 10u)];
        unsigned c2 = (j < 10u) ? c4 : (c4 ^ 1u);
        out[OFF_BOX / 4u + (n * 320u + 300u + j) * 2u + c4] =
            ((const float4*)pred_bboxes)[n * 600u + e * 2u + c2];
        return;
    }
    i -= A_BOX4;
    if (i < A_CLST) {
        unsigned n = i / (20u * 75u), rem = i % (20u * 75u);
        unsigned j = rem / 75u, c4 = rem % 75u;
        unsigned e = (unsigned)g_ent[n * KK + (j % 10u)];
        const float* src = class_logits + n * 90000u + e * 300u;
        float4 v;
        unsigned col = c4 * 4u;
        if (j < 10u) {
            v.x = src[col]; v.y = src[col + 1u];
            v.z = src[col + 2u]; v.w = src[col + 3u];
        } else {
            unsigned c0 = (col      < 150u) ? col + 150u : col - 150u;
            unsigned c1 = (col + 1u < 150u) ? col + 151u : col - 149u;
            unsigned c2 = (col + 2u < 150u) ? col + 152u : col - 148u;
            unsigned c3 = (col + 3u < 150u) ? col + 153u : col - 147u;
            v.x = src[c0]; v.y = src[c1]; v.z = src[c2]; v.w = src[c3];
        }
        out[OFF_CLS / 4u + (n * 320u + 300u + j) * 75u + c4] = v;
        return;
    }
}

// ---------------------------------------------------------------------------
extern "C" void kernel_launch(void* const* d_in, const int* in_sizes, int n_in,
                              void* d_out, int out_size)
{
    const float* aux_rel         = (const float*)d_in[0];
    const float* class_logits    = (const float*)d_in[1];
    const float* pred_bboxes     = (const float*)d_in[2];
    const float* pro_features    = (const float*)d_in[3];
    const float* roi_features    = (const float*)d_in[4];
    const float* so_class_logits = (const float*)d_in[5];
    const float* pred_bboxes_so  = (const float*)d_in[6];
    const float* so_pro          = (const float*)d_in[7];
    const float* so_roi          = (const float*)d_in[8];
    const float* rel_logits      = (const float*)d_in[9];
    const float* rel_feat        = (const float*)d_in[10];
    const unsigned char* vis     = (const unsigned char*)d_in[11];

    mega_kernel<<<NGRID, 256>>>(so_class_logits, rel_logits, class_logits,
                                pred_bboxes, pred_bboxes_so, vis,
                                aux_rel, pro_features, roi_features,
                                so_pro, so_roi, rel_feat,
                                (float*)d_out);
}

// round 14
// speedup vs baseline: 1.3315x; 1.0170x over previous
#include <cuda_runtime.h>

#define NB 16
#define NRR 300
#define CC 150
#define NRL 50
#define KK 10
#define MAXREC 100
#define NT 2700   // 300 * 9
#define NEG_INF (-3.0e38f)
#define FULLM 0xFFFFFFFFu

// Output layout (float elements), return order:
// so_pro_out (16,320,512), boxes_so_out (16,320,8), so_cls_out (16,320,300),
// rel_out (16,320,256), so_roi_out (16,320,12544), vis_out (16,300)
#define OFF_PRO 0
#define OFF_BOX 2621440
#define OFF_CLS 2662400
#define OFF_REL 4198400
#define OFF_ROI 5509120
#define OFF_VIS 69734400

// copy region sizes (float4 tasks); main first, aux at the very end
#define S_ROI4 15052800u
#define S_PRO4   614400u
#define S_CLS4   360000u
#define S_REL4   307200u
#define S_BOX4     9600u
#define TOTM   16344000u
#define A_ROI4  1003520u
#define A_PRO4    40960u
#define A_REL4    20480u
#define A_BOX4      640u
#define A_CLST    24000u
#define TOTC   17433600u

// block layout: select blocks first, then copy blocks (first 1200 of which
// also carry one k1 warp-task each: 1200 blocks * 8 warps = 9600 tasks)
#define SEL_BASE   0
#define COPY_BASE  16
#define NK1BLK     1200
#define NCOPYBLK   68100
#define NGRID      68116
#define N_AUX_BLOCKS 4257   // copy blocks whose range touches [TOTM, TOTC)

__device__ int   g_ent[NB * KK];
__device__ float g_triple[NB * NT];
__device__ int   g_sc[NB * NRR * 3];
__device__ int   g_oc[NB * NRR * 3];
__device__ int   g_mi[NB * NRR];
__device__ float g_pure[NB * NRR];

// completion counters (self-resetting each launch)
__device__ int g_k1done  = 0;
__device__ int g_selpass = 0;
__device__ int g_seldone = 0;
__device__ int g_auxpass = 0;

__device__ __forceinline__ float sigm(float x) { return 1.0f / (1.0f + expf(-x)); }

__device__ __forceinline__ void better(float nv, int ni, float& bv, int& bi) {
    if (nv > bv || (nv == bv && ni < bi)) { bv = nv; bi = ni; }
}

__device__ __forceinline__ void warp_argmax(float& bv, int& bi) {
    #pragma unroll
    for (int off = 16; off > 0; off >>= 1) {
        float ov = __shfl_down_sync(FULLM, bv, off);
        int   oi = __shfl_down_sync(FULLM, bi, off);
        better(ov, oi, bv, bi);
    }
    bv = __shfl_sync(FULLM, bv, 0);
    bi = __shfl_sync(FULLM, bi, 0);
}

// ---------------------------------------------------------------------------
// k1 task: w in [0,4800) = pair, [4800,9600) = entity. One warp per task.
// ---------------------------------------------------------------------------
__device__ void do_k1_task(int w, int lane,
                           const float* __restrict__ so_class_logits,
                           const float* __restrict__ rel_logits,
                           const float* __restrict__ class_logits)
{
    if (w < NB * NRR) {
        const int n = w / NRR, p = w % NRR;
        const float* sl = so_class_logits + (n * NRR + p) * (2 * CC);
        const float* rl = rel_logits + (n * NRR + p) * NRL;

        float sv[5], ov[5]; int sidx[5];
        #pragma unroll
        for (int k = 0; k < 5; k++) {
            int c = lane + 32 * k;
            bool ok = (c < CC);
            sidx[k] = ok ? c : (1 << 30);
            sv[k] = ok ? sl[c] : NEG_INF;
            ov[k] = ok ? sl[CC + c] : NEG_INF;
        }
        float r = (lane < NRL) ? rl[lane] : NEG_INF;
        if (lane + 32 < NRL) r = fmaxf(r, rl[lane + 32]);
        #pragma unroll
        for (int off = 16; off > 0; off >>= 1)
            r = fmaxf(r, __shfl_xor_sync(FULLM, r, off));
        float relm = sigm(r);

        float stv[3]; int sti[3];
        #pragma unroll
        for (int rnd = 0; rnd < 3; rnd++) {
            float bv = NEG_INF; int bi = (1 << 30);
            #pragma unroll
            for (int k = 0; k < 5; k++) better(sv[k], sidx[k], bv, bi);
            warp_argmax(bv, bi);
            stv[rnd] = bv; sti[rnd] = bi;
            #pragma unroll
            for (int k = 0; k < 5; k++) if (sidx[k] == bi) sv[k] = NEG_INF;
        }
        float otv[3]; int oti[3];
        #pragma unroll
        for (int rnd = 0; rnd < 3; rnd++) {
            float bv = NEG_INF; int bi = (1 << 30);
            #pragma unroll
            for (int k = 0; k < 5; k++) better(ov[k], sidx[k], bv, bi);
            warp_argmax(bv, bi);
            otv[rnd] = bv; oti[rnd] = bi;
            #pragma unroll
            for (int k = 0; k < 5; k++) if (sidx[k] == bi) ov[k] = NEG_INF;
        }

        float ss0 = sigm(stv[0]), ss1 = sigm(stv[1]), ss2 = sigm(stv[2]);
        float os0 = sigm(otv[0]), os1 = sigm(otv[1]), os2 = sigm(otv[2]);

        if (lane < 9) {
            int i = lane / 3, j = lane % 3;
            float ssv = (i == 0) ? ss0 : (i == 1) ? ss1 : ss2;
            float oov = (j == 0) ? os0 : (j == 1) ? os1 : os2;
            g_triple[n * NT + p * 9 + lane] = (relm * ssv) * oov;
        }
        if (lane < 3) {
            g_sc[(n * NRR + p) * 3 + lane] = sti[lane];
            g_oc[(n * NRR + p) * 3 + lane] = oti[lane];
        }
    } else if (w < 2 * NB * NRR) {
        const int q = w - NB * NRR;
        const int n = q / NRR, s = q % NRR;
        const float* cl = class_logits + (n * 2 * NRR + 2 * s) * CC;
        float bv = NEG_INF; int bi = (1 << 30);
        #pragma unroll
        for (int k = 0; k < 5; k++) {
            int c = lane + 32 * k;
            if (c < CC) better(cl[c], c, bv, bi);
        }
        warp_argmax(bv, bi);
        if (lane == 0) {
            g_mi[n * NRR + s]   = bi;
            g_pure[n * NRR + s] = sigm(bv);
        }
    }
}

__device__ __forceinline__ void copy_main_task(const float4* __restrict__ src,
                                               float4* __restrict__ out,
                                               unsigned r, unsigned D4,
                                               unsigned off4)
{
    unsigned n = r / (NRR * D4);
    unsigned rem = r - n * (NRR * D4);
    unsigned row = rem / D4;
    unsigned col = rem - row * D4;
    out[off4 + (n * 320u + row) * D4 + col] = src[r];
}

__device__ __forceinline__ unsigned long long make_key(float f, int s) {
    unsigned u = __float_as_uint(f);
    u ^= (u & 0x80000000u) ? 0xFFFFFFFFu : 0x80000000u;
    return ((unsigned long long)u << 32) | (unsigned)(1023 - s);
}

// ---------------------------------------------------------------------------
// Mega-kernel
// ---------------------------------------------------------------------------
__global__ __launch_bounds__(256, 8) void mega_kernel(
    const float* __restrict__ so_class_logits,  // (16,300,300)
    const float* __restrict__ rel_logits,       // (16,300,50)
    const float* __restrict__ class_logits,     // (16,600,150)
    const float* __restrict__ pred_bboxes,      // (16,600,4)
    const float* __restrict__ pred_bboxes_so,   // (16,300,8)
    const unsigned char* __restrict__ vis,      // (16,300)
    const float* __restrict__ aux_rel,          // (16,300,512)
    const float* __restrict__ pro_features,     // (16,300,512)
    const float* __restrict__ roi_features,     // (16,300,12544)
    const float* __restrict__ so_pro,           // (16,300,512)
    const float* __restrict__ so_roi,           // (16,300,12544)
    const float* __restrict__ rel_feat,         // (16,300,256)
    float* __restrict__ outf)
{
    __shared__ float sh_triple[NT];
    __shared__ int   sh_selt[MAXREC];
    __shared__ int   sh_eq[128];
    __shared__ int   sh_cnt, sh_cnt_gt, sh_cnt_eq;
    __shared__ int   sel_class[2 * MAXREC];
    __shared__ float sel_box[2 * MAXREC * 4];
    __shared__ float sel_a2[2 * MAXREC];
    __shared__ float sh_score[NRR];
    __shared__ unsigned char sh_sel[NRR];
    __shared__ int   sh_ent[KK];
    __shared__ unsigned long long sh_key;

    const int bid = blockIdx.x;
    const int tid = threadIdx.x;
    const int wid = tid >> 5;
    const int lane = tid & 31;
    float4* out = (float4*)outf;

    if (bid < COPY_BASE) {
        // ================= select blocks (one per image) =================
        const int n = bid - SEL_BASE;

        // wait for the 1200 k1-carrier copy blocks
        if (tid == 0) {
            while (atomicAdd(&g_k1done, 0) < NK1BLK) {}
            __threadfence();
            int v = atomicAdd(&g_selpass, 1);
            if (v == NB - 1) {             // last select block past the spin
                atomicExch(&g_selpass, 0);
                atomicExch(&g_k1done, 0);
            }
        }
        __syncthreads();

        for (int t = tid; t < NT; t += 256) sh_triple[t] = g_triple[n * NT + t];
        for (int s = tid; s < NRR; s += 256) sh_sel[s] = 0;
        __syncthreads();

        // top-100 threshold via binary search on float bits (values in (0,1))
        unsigned lo = 0u, hi = 0x3F800000u;
        while (lo < hi) {
            unsigned mid = lo + ((hi - lo + 1u) >> 1);
            if (tid == 0) sh_cnt = 0;
            __syncthreads();
            int local = 0;
            for (int t = tid; t < NT; t += 256)
                local += (__float_as_uint(sh_triple[t]) >= mid) ? 1 : 0;
            #pragma unroll
            for (int off = 16; off > 0; off >>= 1)
                local += __shfl_xor_sync(FULLM, local, off);
            if (lane == 0 && local) atomicAdd(&sh_cnt, local);
            __syncthreads();
            if (sh_cnt >= MAXREC) lo = mid; else hi = mid - 1u;
            __syncthreads();
        }
        const unsigned thr = lo;

        if (tid == 0) { sh_cnt_gt = 0; sh_cnt_eq = 0; }
        __syncthreads();
        for (int t = tid; t < NT; t += 256) {
            unsigned b = __float_as_uint(sh_triple[t]);
            if (b > thr) {
                int p = atomicAdd(&sh_cnt_gt, 1);
                if (p < MAXREC) sh_selt[p] = t;
            } else if (b == thr) {
                int p = atomicAdd(&sh_cnt_eq, 1);
                if (p < 128) sh_eq[p] = t;
            }
        }
        __syncthreads();
        if (tid == 0) {
            int c1 = sh_cnt_gt; if (c1 > MAXREC) c1 = MAXREC;
            int need = MAXREC - c1;
            int ne = sh_cnt_eq; if (ne > 128) ne = 128;
            for (int a = 1; a < ne; a++) {   // ties: lowest index first
                int key = sh_eq[a]; int b = a - 1;
                while (b >= 0 && sh_eq[b] > key) { sh_eq[b + 1] = sh_eq[b]; b--; }
                sh_eq[b + 1] = key;
            }
            for (int a = 0; a < need && a < ne; a++) sh_selt[c1 + a] = sh_eq[a];
        }
        __syncthreads();

        // build selected (class, box, area): 200 entries
        if (tid < MAXREC) {
            int t = sh_selt[tid];
            int p = t / 9, r2 = t % 9, si = r2 / 3, oj = r2 % 3;
            const float* b = pred_bboxes_so + (n * NRR + p) * 8;
            sel_class[2 * tid]     = g_sc[(n * NRR + p) * 3 + si];
            sel_class[2 * tid + 1] = g_oc[(n * NRR + p) * 3 + oj];
            #pragma unroll
            for (int c = 0; c < 4; c++) {
                sel_box[(2 * tid) * 4 + c]     = b[c];
                sel_box[(2 * tid + 1) * 4 + c] = b[4 + c];
            }
            sel_a2[2 * tid]     = (b[3] - b[1] + 1.f) * (b[2] - b[0] + 1.f);
            sel_a2[2 * tid + 1] = (b[7] - b[5] + 1.f) * (b[6] - b[4] + 1.f);
        }
        __syncthreads();

        // entity scores: warp per entity (8 warps), candidates over lanes
        for (int s = wid; s < NRR; s += 8) {
            int   mi   = g_mi[n * NRR + s];
            float pure = g_pure[n * NRR + s];
            const float* bp = pred_bboxes + (n * 2 * NRR + 2 * s) * 4;
            float x1 = bp[0], y1 = bp[1], x2 = bp[2], y2 = bp[3];
            float a1 = (y2 - y1 + 1.f) * (x2 - x1 + 1.f);
            bool fhit = false;
            for (int m = lane; m < 2 * MAXREC; m += 32) {
                if (sel_class[m] == mi) {
                    float lx = fmaxf(x1, sel_box[m * 4 + 0]);
                    float ly = fmaxf(y1, sel_box[m * 4 + 1]);
                    float rx = fminf(x2, sel_box[m * 4 + 2]);
                    float ry = fminf(y2, sel_box[m * 4 + 3]);
                    float wdt = fmaxf(rx - lx, 0.f), hgt = fmaxf(ry - ly, 0.f);
                    float inter = wdt * hgt;
                    if (inter / (a1 + sel_a2[m] - inter) >= 0.5f) fhit = true;
                }
            }
            bool hit = __any_sync(FULLM, fhit);
            if (lane == 0)
                sh_score[s] = pure - (hit ? 2.f : 0.f)
                                   - (vis[n * NRR + s] ? 2.f : 0.f);
        }
        __syncthreads();

        // top-10 via packed atomicMax (score desc, index asc)
        unsigned long long key0 = 0ull, key1 = 0ull;
        int s1 = tid + 256;
        if (tid < NRR) key0 = make_key(sh_score[tid], tid);
        if (s1 < NRR)  key1 = make_key(sh_score[s1], s1);
        for (int k = 0; k < KK; k++) {
            if (tid == 0) sh_key = 0ull;
            __syncthreads();
            if (tid < NRR && !sh_sel[tid]) atomicMax(&sh_key, key0);
            if (s1 < NRR && !sh_sel[s1])  atomicMax(&sh_key, key1);
            __syncthreads();
            if (tid == 0) {
                int s = 1023 - (int)(unsigned)(sh_key & 0xFFFFFFFFull);
                sh_ent[k] = s;
                sh_sel[s] = 1;
            }
            __syncthreads();
        }
        if (tid == 0) {
            for (int a = 1; a < KK; a++) {   // sort ascending
                int key = sh_ent[a]; int b = a - 1;
                while (b >= 0 && sh_ent[b] > key) { sh_ent[b + 1] = sh_ent[b]; b--; }
                sh_ent[b + 1] = key;
            }
            #pragma unroll
            for (int a = 0; a < KK; a++) g_ent[n * KK + a] = sh_ent[a];
            __threadfence();
            atomicAdd(&g_seldone, 1);   // release for aux copy blocks
        }

        // vis_out
        for (int s = tid; s < NRR; s += 256)
            outf[OFF_VIS + n * NRR + s] =
                (vis[n * NRR + s] || sh_sel[s]) ? 1.0f : 0.0f;
        return;
    }

    // ================= copy blocks =================
    const unsigned cb = (unsigned)(bid - COPY_BASE);

    // first 1200 copy blocks carry one k1 warp-task each (8 warps x 1200 = 9600)
    if (cb < NK1BLK) {
        do_k1_task((int)cb * 8 + wid, lane,
                   so_class_logits, rel_logits, class_logits);
        __syncthreads();
        if (tid == 0) {
            __threadfence();
            atomicAdd(&g_k1done, 1);
        }
    }

    const unsigned base_i = cb * 256u;

    // aux-region blocks must wait for selection (scheduled many waves later,
    // so the spin is normally already satisfied)
    if (base_i + 255u >= TOTM) {
        if (tid == 0) {
            while (atomicAdd(&g_seldone, 0) < NB) {}
            __threadfence();
            int v = atomicAdd(&g_auxpass, 1);
            if (v == N_AUX_BLOCKS - 1) {    // last aux block past the spin
                atomicExch(&g_auxpass, 0);
                atomicExch(&g_seldone, 0);
            }
        }
        __syncthreads();
    }

    unsigned i = base_i + (unsigned)tid;

    // ---- main regions (selection-independent) ----
    if (i < S_ROI4) { copy_main_task((const float4*)so_roi, out, i, 3136u, OFF_ROI / 4u); return; }
    i -= S_ROI4;
    if (i < S_PRO4) { copy_main_task((const float4*)so_pro, out, i, 128u, OFF_PRO / 4u); return; }
    i -= S_PRO4;
    if (i < S_CLS4) { copy_main_task((const float4*)so_class_logits, out, i, 75u, OFF_CLS / 4u); return; }
    i -= S_CLS4;
    if (i < S_REL4) { copy_main_task((const float4*)rel_feat, out, i, 64u, OFF_REL / 4u); return; }
    i -= S_REL4;
    if (i < S_BOX4) { copy_main_task((const float4*)pred_bboxes_so, out, i, 2u, OFF_BOX / 4u); return; }
    i -= S_BOX4;

    // ---- aux regions (gathered rows 300..319) ----
    if (i < A_ROI4) {
        unsigned n = i / (20u * 3136u), rem = i % (20u * 3136u);
        unsigned j = rem / 3136u, c4 = rem % 3136u;
        unsigned e = (unsigned)g_ent[n * KK + (j % 10u)];
        unsigned c2 = (j < 10u) ? c4 : (c4 < 1568u ? c4 + 1568u : c4 - 1568u);
        out[OFF_ROI / 4u + (n * 320u + 300u + j) * 3136u + c4] =
            ((const float4*)roi_features)[(n * 300u + e) * 3136u + c2];
        return;
    }
    i -= A_ROI4;
    if (i < A_PRO4) {
        unsigned n = i / (20u * 128u), rem = i % (20u * 128u);
        unsigned j = rem / 128u, c4 = rem % 128u;
        unsigned e = (unsigned)g_ent[n * KK + (j % 10u)];
        unsigned c2 = (j < 10u) ? c4 : ((c4 + 64u) & 127u);
        out[OFF_PRO / 4u + (n * 320u + 300u + j) * 128u + c4] =
            ((const float4*)pro_features)[(n * 300u + e) * 128u + c2];
        return;
    }
    i -= A_PRO4;
    if (i < A_REL4) {
        unsigned n = i / (20u * 64u), rem = i % (20u * 64u);
        unsigned j = rem / 64u, c4 = rem % 64u;
        unsigned e = (unsigned)g_ent[n * KK + (j % 10u)];
        unsigned c2 = c4 + ((j < 10u) ? 0u : 64u);
        out[OFF_REL / 4u + (n * 320u + 300u + j) * 64u + c4] =
            ((const float4*)aux_rel)[(n * 300u + e) * 128u + c2];
        return;
    }
    i -= A_REL4;
    if (i < A_BOX4) {
        unsigned n = i / (20u * 2u), rem = i % (20u * 2u);
        unsigned j = rem / 2u, c4 = rem % 2u;
        unsigned e = (unsigned)g_ent[n * KK + (j % 10u)];
        unsigned c2 = (j < 10u) ? c4 : (c4 ^ 1u);
        out[OFF_BOX / 4u + (n * 320u + 300u + j) * 2u + c4] =
            ((const float4*)pred_bboxes)[n * 600u + e * 2u + c2];
        return;
    }
    i -= A_BOX4;
    if (i < A_CLST) {
        unsigned n = i / (20u * 75u), rem = i % (20u * 75u);
        unsigned j = rem / 75u, c4 = rem % 75u;
        unsigned e = (unsigned)g_ent[n * KK + (j % 10u)];
        const float* src = class_logits + n * 90000u + e * 300u;
        float4 v;
        unsigned col = c4 * 4u;
        if (j < 10u) {
            v.x = src[col]; v.y = src[col + 1u];
            v.z = src[col + 2u]; v.w = src[col + 3u];
        } else {
            unsigned c0 = (col      < 150u) ? col + 150u : col - 150u;
            unsigned c1 = (col + 1u < 150u) ? col + 151u : col - 149u;
            unsigned c2 = (col + 2u < 150u) ? col + 152u : col - 148u;
            unsigned c3 = (col + 3u < 150u) ? col + 153u : col - 147u;
            v.x = src[c0]; v.y = src[c1]; v.z = src[c2]; v.w = src[c3];
        }
        out[OFF_CLS / 4u + (n * 320u + 300u + j) * 75u + c4] = v;
        return;
    }
}

// ---------------------------------------------------------------------------
extern "C" void kernel_launch(void* const* d_in, const int* in_sizes, int n_in,
                              void* d_out, int out_size)
{
    const float* aux_rel         = (const float*)d_in[0];
    const float* class_logits    = (const float*)d_in[1];
    const float* pred_bboxes     = (const float*)d_in[2];
    const float* pro_features    = (const float*)d_in[3];
    const float* roi_features    = (const float*)d_in[4];
    const float* so_class_logits = (const float*)d_in[5];
    const float* pred_bboxes_so  = (const float*)d_in[6];
    const float* so_pro          = (const float*)d_in[7];
    const float* so_roi          = (const float*)d_in[8];
    const float* rel_logits      = (const float*)d_in[9];
    const float* rel_feat        = (const float*)d_in[10];
    const unsigned char* vis     = (const unsigned char*)d_in[11];

    mega_kernel<<<NGRID, 256>>>(so_class_logits, rel_logits, class_logits,
                                pred_bboxes, pred_bboxes_so, vis,
                                aux_rel, pro_features, roi_features,
                                so_pro, so_roi, rel_feat,
                                (float*)d_out);
}